// round 1
// baseline (speedup 1.0000x reference)
#include <cuda_runtime.h>
#include <cuda_bf16.h>
#include <math.h>

// Problem constants
#define B   64
#define T   100
#define S   1024
#define IN  256
#define TRG 512
#define ENC 512
#define G4  2048   // 4*TRG

// Output layout offsets (floats), flatten order:
// output_, hT, cT, haT, attns, paT, p_gen, past_dehy, loss_cv
#define OUT_OFF   0
#define HT_OFF    3276800      // B*T*TRG
#define CT_OFF    3309568
#define HAT_OFF   3342336
#define ATTN_OFF  3375104
#define PAT_OFF   9928704      // + T*B*S
#define PGEN_OFF  9994240      // + B*S
#define PDH_OFF   10000640     // + B*T
#define LOSS_OFF  10033408     // + B*TRG

// ---------------- device state ----------------
__device__ float g_encproj[(size_t)B * S * TRG];   // 134 MB
__device__ float g_h[2][B * TRG];
__device__ float g_c[2][B * TRG];
__device__ float g_ha[2][B * TRG];
__device__ float g_pa[2][B * S];
__device__ float g_gates[B * G4];
__device__ float g_hde[B * TRG];
__device__ float g_attn[B * S];
__device__ float g_cenc[B * TRG];

__device__ __forceinline__ float warp_red_sum(float v) {
#pragma unroll
    for (int o = 16; o; o >>= 1) v += __shfl_xor_sync(0xffffffffu, v, o);
    return v;
}
__device__ __forceinline__ float sigmoidf(float x) { return 1.0f / (1.0f + expf(-x)); }

// ---------------- init ----------------
__global__ void k_init(const float* __restrict__ h0, const float* __restrict__ c0,
                       const float* __restrict__ h_attn, const float* __restrict__ past_attn) {
    int i = blockIdx.x * blockDim.x + threadIdx.x;
    if (i < B * TRG) { g_h[0][i] = h0[i]; g_c[0][i] = c0[i]; g_ha[0][i] = h_attn[i]; }
    if (i < B * S) g_pa[0][i] = past_attn[i];
}

// ---------------- enc_proj GEMM: C[M=B*S, N=512] = A[M,512] @ W[512,512]^T + bias ----------------
// BM=128, BN=64, BK=16, 256 threads, each 8x4
__global__ void k_encproj(const float* __restrict__ A, const float* __restrict__ W,
                          const float* __restrict__ bias) {
    __shared__ float As[16][128 + 4];
    __shared__ float Bs[16][64 + 4];
    const int bm = blockIdx.y * 128;
    const int bn = blockIdx.x * 64;
    const int tid = threadIdx.x;
    const int ty = tid / 16, tx = tid % 16;

    float acc[8][4];
#pragma unroll
    for (int i = 0; i < 8; i++)
#pragma unroll
        for (int j = 0; j < 4; j++) acc[i][j] = 0.f;

    for (int k0 = 0; k0 < 512; k0 += 16) {
        // Load A tile: 128x16 = 512 float4 slots
#pragma unroll
        for (int l = 0; l < 2; l++) {
            int idx = tid + l * 256;
            int r = idx >> 2, c4 = idx & 3;
            float4 v = *(const float4*)&A[(size_t)(bm + r) * 512 + k0 + c4 * 4];
            As[c4 * 4 + 0][r] = v.x; As[c4 * 4 + 1][r] = v.y;
            As[c4 * 4 + 2][r] = v.z; As[c4 * 4 + 3][r] = v.w;
        }
        // Load W tile: 64x16 = 256 float4 slots
        {
            int r = tid >> 2, c4 = tid & 3;
            float4 v = *(const float4*)&W[(size_t)(bn + r) * 512 + k0 + c4 * 4];
            Bs[c4 * 4 + 0][r] = v.x; Bs[c4 * 4 + 1][r] = v.y;
            Bs[c4 * 4 + 2][r] = v.z; Bs[c4 * 4 + 3][r] = v.w;
        }
        __syncthreads();
#pragma unroll
        for (int k = 0; k < 16; k++) {
            float a[8], bb[4];
#pragma unroll
            for (int i = 0; i < 8; i++) a[i] = As[k][ty * 8 + i];
#pragma unroll
            for (int j = 0; j < 4; j++) bb[j] = Bs[k][tx * 4 + j];
#pragma unroll
            for (int i = 0; i < 8; i++)
#pragma unroll
                for (int j = 0; j < 4; j++) acc[i][j] = fmaf(a[i], bb[j], acc[i][j]);
        }
        __syncthreads();
    }
#pragma unroll
    for (int i = 0; i < 8; i++) {
        size_t row = (size_t)(bm + ty * 8 + i) * 512;
#pragma unroll
        for (int j = 0; j < 4; j++) {
            int col = bn + tx * 4 + j;
            g_encproj[row + col] = acc[i][j] + bias[col];
        }
    }
}

// ---------------- K1: gates = [x_t, ha] @ w_ih^T + b_ih + h @ w_hh^T + b_hh ----------------
// grid (G4/8=256, B), block 256 (8 warps, warp per gate output)
__global__ void k_gates(const float* __restrict__ input_, const float* __restrict__ w_ih,
                        const float* __restrict__ b_ih, const float* __restrict__ w_hh,
                        const float* __restrict__ b_hh, int cur, int t) {
    __shared__ __align__(16) float xv[IN + TRG + TRG];   // 1280
    const int b = blockIdx.y;
    const int tid = threadIdx.x;
    const float* xt = input_ + ((size_t)b * T + t) * IN;
    if (tid < IN) xv[tid] = xt[tid];
    for (int i = tid; i < TRG; i += 256) xv[IN + i]       = g_ha[cur][b * TRG + i];
    for (int i = tid; i < TRG; i += 256) xv[IN + TRG + i] = g_h[cur][b * TRG + i];
    __syncthreads();

    const int warp = tid >> 5, lane = tid & 31;
    const int g = blockIdx.x * 8 + warp;
    const float4* wi = (const float4*)(w_ih + (size_t)g * (IN + TRG));
    const float4* xv4 = (const float4*)xv;
    float acc = 0.f;
#pragma unroll
    for (int i = 0; i < 6; i++) {       // 768/4/32 = 6
        int idx = lane + i * 32;
        float4 w4 = wi[idx], x4 = xv4[idx];
        acc += w4.x * x4.x + w4.y * x4.y + w4.z * x4.z + w4.w * x4.w;
    }
    const float4* wh = (const float4*)(w_hh + (size_t)g * TRG);
    const float4* hv4 = (const float4*)(xv + IN + TRG);
#pragma unroll
    for (int i = 0; i < 4; i++) {       // 512/4/32 = 4
        int idx = lane + i * 32;
        float4 w4 = wh[idx], x4 = hv4[idx];
        acc += w4.x * x4.x + w4.y * x4.y + w4.z * x4.z + w4.w * x4.w;
    }
    acc = warp_red_sum(acc);
    if (lane == 0) g_gates[b * G4 + g] = acc + b_ih[g] + b_hh[g];
}

// ---------------- K1b: LSTM pointwise ----------------
__global__ void k_lstm(int cur) {
    const int b = blockIdx.x, j = threadIdx.x;
    const int nxt = cur ^ 1;
    const float* g = g_gates + b * G4;
    float i_ = g[j], f_ = g[TRG + j], gg = g[2 * TRG + j], o_ = g[3 * TRG + j];
    float cn = sigmoidf(f_) * g_c[cur][b * TRG + j] + sigmoidf(i_) * tanhf(gg);
    float hn = sigmoidf(o_) * tanhf(cn);
    g_c[nxt][b * TRG + j] = cn;
    g_h[nxt][b * TRG + j] = hn;
}

// ---------------- K1c: hde = h_new @ w_de^T ----------------
// grid (64, B), block 256 (8 warps, warp per output)
__global__ void k_hde(const float* __restrict__ w_de, int cur) {
    __shared__ __align__(16) float hv[TRG];
    const int b = blockIdx.y, tid = threadIdx.x;
    const int nxt = cur ^ 1;
    for (int i = tid; i < TRG; i += 256) hv[i] = g_h[nxt][b * TRG + i];
    __syncthreads();
    const int warp = tid >> 5, lane = tid & 31;
    const int j = blockIdx.x * 8 + warp;
    const float4* w = (const float4*)(w_de + (size_t)j * TRG);
    const float4* h4 = (const float4*)hv;
    float acc = 0.f;
#pragma unroll
    for (int i = 0; i < 4; i++) {
        int idx = lane + i * 32;
        float4 w4 = w[idx], x4 = h4[idx];
        acc += w4.x * x4.x + w4.y * x4.y + w4.z * x4.z + w4.w * x4.w;
    }
    acc = warp_red_sum(acc);
    if (lane == 0) g_hde[b * TRG + j] = acc;
}

// ---------------- K2: attn_ee[b,s] = sum_h tanh(ep + hde + pa*cv) * warp_w ----------------
// grid (S/8=128, B), block 256 (warp per s)
__global__ void k_attnee(const float* __restrict__ cv_w, const float* __restrict__ warp_w, int cur) {
    __shared__ __align__(16) float sh_hde[TRG], sh_cv[TRG], sh_w[TRG];
    const int b = blockIdx.y, tid = threadIdx.x;
    for (int i = tid; i < TRG; i += 256) {
        sh_hde[i] = g_hde[b * TRG + i];
        sh_cv[i]  = cv_w[i];
        sh_w[i]   = warp_w[i];
    }
    __syncthreads();
    const int warp = tid >> 5, lane = tid & 31;
    const int s = blockIdx.x * 8 + warp;
    const float pa = g_pa[cur][b * S + s];
    const float4* ep = (const float4*)(g_encproj + ((size_t)b * S + s) * TRG);
    const float4* hd4 = (const float4*)sh_hde;
    const float4* cv4 = (const float4*)sh_cv;
    const float4* ww4 = (const float4*)sh_w;
    float acc = 0.f;
#pragma unroll
    for (int i = 0; i < 4; i++) {
        int idx = lane + i * 32;
        float4 e = ep[idx], hd = hd4[idx], cv = cv4[idx], ww = ww4[idx];
        acc += tanhf(e.x + hd.x + pa * cv.x) * ww.x;
        acc += tanhf(e.y + hd.y + pa * cv.y) * ww.y;
        acc += tanhf(e.z + hd.z + pa * cv.z) * ww.z;
        acc += tanhf(e.w + hd.w + pa * cv.w) * ww.w;
    }
    acc = warp_red_sum(acc);
    if (lane == 0) g_attn[b * S + s] = acc;
}

// ---------------- K3: softmax over S, pa update, attns output, zero c_enc ----------------
// grid B, block 1024
__global__ void k_softmax(float* __restrict__ out_attn_t, int cur) {
    const int b = blockIdx.x, s = threadIdx.x;
    const int lane = s & 31, warp = s >> 5;
    const int nxt = cur ^ 1;
    __shared__ float red[32];
    float v = g_attn[b * S + s];
    // block max
    float m = v;
#pragma unroll
    for (int o = 16; o; o >>= 1) m = fmaxf(m, __shfl_xor_sync(0xffffffffu, m, o));
    if (lane == 0) red[warp] = m;
    __syncthreads();
    if (warp == 0) {
        float mm = red[lane];
#pragma unroll
        for (int o = 16; o; o >>= 1) mm = fmaxf(mm, __shfl_xor_sync(0xffffffffu, mm, o));
        if (lane == 0) red[0] = mm;
    }
    __syncthreads();
    m = red[0];
    __syncthreads();
    float e = expf(v - m);
    // block sum
    float sum = warp_red_sum(e);
    if (lane == 0) red[warp] = sum;
    __syncthreads();
    if (warp == 0) {
        float ss = red[lane];
#pragma unroll
        for (int o = 16; o; o >>= 1) ss += __shfl_xor_sync(0xffffffffu, ss, o);
        if (lane == 0) red[0] = ss;
    }
    __syncthreads();
    float a = e / red[0];
    g_attn[b * S + s] = a;
    out_attn_t[(size_t)b * S + s] = a;
    g_pa[nxt][b * S + s] = g_pa[cur][b * S + s] + a;
    if (s < TRG) g_cenc[b * TRG + s] = 0.f;
}

// ---------------- K4: c_enc[b,e] += sum_s attn[b,s] * enc[b,s,e] ----------------
// grid (8, B), block 512 (e), 128 s per block
__global__ void k_cenc(const float* __restrict__ enc) {
    __shared__ float sat[128];
    const int b = blockIdx.y;
    const int s0 = blockIdx.x * 128;
    const int e = threadIdx.x;
    if (e < 128) sat[e] = g_attn[b * S + s0 + e];
    __syncthreads();
    float acc = 0.f;
    const float* ebase = enc + ((size_t)b * S + s0) * ENC + e;
#pragma unroll 4
    for (int s = 0; s < 128; s++) acc = fmaf(sat[s], ebase[(size_t)s * ENC], acc);
    atomicAdd(&g_cenc[b * TRG + e], acc);
}

// ---------------- K5: ha_new = [c_enc, h_new] @ w_ao^T + b_ao ; write output_ ----------------
// grid (64, B), block 256
__global__ void k_ha(const float* __restrict__ w_ao, const float* __restrict__ b_ao,
                     float* __restrict__ out, int cur, int t) {
    __shared__ __align__(16) float v[ENC + TRG];   // 1024
    const int b = blockIdx.y, tid = threadIdx.x;
    const int nxt = cur ^ 1;
    for (int i = tid; i < TRG; i += 256) v[i]       = g_cenc[b * TRG + i];
    for (int i = tid; i < TRG; i += 256) v[TRG + i] = g_h[nxt][b * TRG + i];
    __syncthreads();
    const int warp = tid >> 5, lane = tid & 31;
    const int j = blockIdx.x * 8 + warp;
    const float4* w = (const float4*)(w_ao + (size_t)j * (ENC + TRG));
    const float4* v4 = (const float4*)v;
    float acc = 0.f;
#pragma unroll
    for (int i = 0; i < 8; i++) {
        int idx = lane + i * 32;
        float4 w4 = w[idx], x4 = v4[idx];
        acc += w4.x * x4.x + w4.y * x4.y + w4.z * x4.z + w4.w * x4.w;
    }
    acc = warp_red_sum(acc);
    if (lane == 0) {
        float r = acc + b_ao[j];
        g_ha[nxt][b * TRG + j] = r;
        out[OUT_OFF + ((size_t)b * T + t) * TRG + j] = r;
    }
}

// ---------------- K6: p_gen = sigmoid([x_t, h_new, c_enc] @ w_pt^T + b_pt) ----------------
// grid 8, block 256 (warp per b)
__global__ void k_pgen(const float* __restrict__ input_, const float* __restrict__ w_pt,
                       const float* __restrict__ b_pt, float* __restrict__ out, int cur, int t) {
    const int tid = threadIdx.x;
    const int warp = tid >> 5, lane = tid & 31;
    const int b = blockIdx.x * 8 + warp;
    const int nxt = cur ^ 1;
    const float* xt = input_ + ((size_t)b * T + t) * IN;
    float acc = 0.f;
    for (int k = lane; k < IN; k += 32)  acc = fmaf(w_pt[k], xt[k], acc);
    for (int k = lane; k < TRG; k += 32) acc = fmaf(w_pt[IN + k], g_h[nxt][b * TRG + k], acc);
    for (int k = lane; k < TRG; k += 32) acc = fmaf(w_pt[IN + TRG + k], g_cenc[b * TRG + k], acc);
    acc = warp_red_sum(acc);
    if (lane == 0) out[PGEN_OFF + (size_t)b * T + t] = sigmoidf(acc + b_pt[0]);
}

// ---------------- finalize: hT, cT, haT, paT, past_dehy passthrough, loss ----------------
__global__ void k_final(float* __restrict__ out, const float* __restrict__ past_dehy) {
    int i = blockIdx.x * blockDim.x + threadIdx.x;
    if (i < B * TRG) {
        out[HT_OFF + i]  = g_h[0][i];
        out[CT_OFF + i]  = g_c[0][i];
        out[HAT_OFF + i] = g_ha[0][i];
        out[PDH_OFF + i] = past_dehy[i];
    }
    if (i < B * S) out[PAT_OFF + i] = g_pa[0][i];
    if (i == 0) out[LOSS_OFF] = 0.f;
}

// ---------------- launch ----------------
extern "C" void kernel_launch(void* const* d_in, const int* in_sizes, int n_in,
                              void* d_out, int out_size) {
    const float* input_    = (const float*)d_in[1];
    const float* h0        = (const float*)d_in[2];
    const float* c0        = (const float*)d_in[3];
    const float* h_attn    = (const float*)d_in[4];
    const float* enc       = (const float*)d_in[5];
    const float* past_attn = (const float*)d_in[6];
    const float* past_dehy = (const float*)d_in[7];
    const float* w_ih      = (const float*)d_in[8];
    const float* b_ih      = (const float*)d_in[9];
    const float* w_hh      = (const float*)d_in[10];
    const float* b_hh      = (const float*)d_in[11];
    const float* w_en      = (const float*)d_in[12];
    const float* b_en      = (const float*)d_in[13];
    const float* w_de      = (const float*)d_in[14];
    const float* w_cv      = (const float*)d_in[15];
    const float* w_warp    = (const float*)d_in[16];
    const float* w_ao      = (const float*)d_in[17];
    const float* b_ao      = (const float*)d_in[18];
    const float* w_pt      = (const float*)d_in[19];
    const float* b_pt      = (const float*)d_in[20];
    float* out = (float*)d_out;

    k_init<<<(B * S + 255) / 256, 256>>>(h0, c0, h_attn, past_attn);
    k_encproj<<<dim3(TRG / 64, (B * S) / 128), 256>>>(enc, w_en, b_en);

    for (int t = 0; t < T; t++) {
        int cur = t & 1;
        k_gates<<<dim3(G4 / 8, B), 256>>>(input_, w_ih, b_ih, w_hh, b_hh, cur, t);
        k_lstm<<<B, TRG>>>(cur);
        k_hde<<<dim3(TRG / 8, B), 256>>>(w_de, cur);
        k_attnee<<<dim3(S / 8, B), 256>>>(w_cv, w_warp, cur);
        k_softmax<<<B, S>>>(out + ATTN_OFF + (size_t)t * B * S, cur);
        k_cenc<<<dim3(8, B), 512>>>(enc);
        k_ha<<<dim3(TRG / 8, B), 256>>>(w_ao, b_ao, out, cur, t);
        k_pgen<<<B / 8, 256>>>(input_, w_pt, b_pt, out, cur, t);
    }
    k_final<<<(B * S + 255) / 256, 256>>>(out, past_dehy);
}

// round 2
// speedup vs baseline: 1.3400x; 1.3400x over previous
#include <cuda_runtime.h>
#include <cuda_fp16.h>
#include <math.h>

// Problem constants
#define B   64
#define T   100
#define S   1024
#define IN  256
#define TRG 512
#define ENC 512
#define G4  2048   // 4*TRG

// Output layout offsets (floats)
#define OUT_OFF   0
#define HT_OFF    3276800
#define CT_OFF    3309568
#define HAT_OFF   3342336
#define ATTN_OFF  3375104
#define PAT_OFF   9928704
#define PGEN_OFF  9994240
#define PDH_OFF   10000640
#define LOSS_OFF  10033408

// ---------------- device state ----------------
__device__ __half  g_encproj_h[(size_t)B * S * TRG];   // 67 MB
__device__ __half  g_enc_h[(size_t)B * S * ENC];       // 67 MB fp16 cache of encoder_hy
__device__ float g_h[2][B * TRG];
__device__ float g_c[2][B * TRG];
__device__ float g_ha[2][B * TRG];
__device__ float g_pa[2][B * S];
__device__ float g_gates4[4][B * G4];                  // split-K partials
__device__ float g_hde[B * TRG];
__device__ float g_attn[B * S];
__device__ float g_cenc4[4][B * TRG];                  // cenc partials (deterministic)

__device__ __forceinline__ float warp_red_sum(float v) {
#pragma unroll
    for (int o = 16; o; o >>= 1) v += __shfl_xor_sync(0xffffffffu, v, o);
    return v;
}
__device__ __forceinline__ float sigmoidf_(float x) { return 1.0f / (1.0f + expf(-x)); }
__device__ __forceinline__ float tanh_ap(float x) {
    float y; asm("tanh.approx.f32 %0, %1;" : "=f"(y) : "f"(x)); return y;
}

// ---------------- init ----------------
__global__ void k_init(const float* __restrict__ h0, const float* __restrict__ c0,
                       const float* __restrict__ h_attn, const float* __restrict__ past_attn) {
    int i = blockIdx.x * blockDim.x + threadIdx.x;
    if (i < B * TRG) { g_h[0][i] = h0[i]; g_c[0][i] = c0[i]; g_ha[0][i] = h_attn[i]; }
    if (i < B * S) g_pa[0][i] = past_attn[i];
}

// ---------------- fp16 conversion of encoder_hy ----------------
__global__ void k_conv(const float* __restrict__ enc) {
    size_t i = ((size_t)blockIdx.x * blockDim.x + threadIdx.x) * 4;
    float4 v = *(const float4*)&enc[i];
    __half2* dst = (__half2*)&g_enc_h[i];
    dst[0] = __floats2half2_rn(v.x, v.y);
    dst[1] = __floats2half2_rn(v.z, v.w);
}

// ---------------- enc_proj GEMM: C[B*S, 512] = A @ W^T + bias, fp16 out ----------------
__global__ void k_encproj(const float* __restrict__ A, const float* __restrict__ W,
                          const float* __restrict__ bias) {
    __shared__ float As[16][128 + 4];
    __shared__ float Bs[16][64 + 4];
    const int bm = blockIdx.y * 128;
    const int bn = blockIdx.x * 64;
    const int tid = threadIdx.x;
    const int ty = tid / 16, tx = tid % 16;

    float acc[8][4];
#pragma unroll
    for (int i = 0; i < 8; i++)
#pragma unroll
        for (int j = 0; j < 4; j++) acc[i][j] = 0.f;

    for (int k0 = 0; k0 < 512; k0 += 16) {
#pragma unroll
        for (int l = 0; l < 2; l++) {
            int idx = tid + l * 256;
            int r = idx >> 2, c4 = idx & 3;
            float4 v = *(const float4*)&A[(size_t)(bm + r) * 512 + k0 + c4 * 4];
            As[c4 * 4 + 0][r] = v.x; As[c4 * 4 + 1][r] = v.y;
            As[c4 * 4 + 2][r] = v.z; As[c4 * 4 + 3][r] = v.w;
        }
        {
            int r = tid >> 2, c4 = tid & 3;
            float4 v = *(const float4*)&W[(size_t)(bn + r) * 512 + k0 + c4 * 4];
            Bs[c4 * 4 + 0][r] = v.x; Bs[c4 * 4 + 1][r] = v.y;
            Bs[c4 * 4 + 2][r] = v.z; Bs[c4 * 4 + 3][r] = v.w;
        }
        __syncthreads();
#pragma unroll
        for (int k = 0; k < 16; k++) {
            float a[8], bb[4];
#pragma unroll
            for (int i = 0; i < 8; i++) a[i] = As[k][ty * 8 + i];
#pragma unroll
            for (int j = 0; j < 4; j++) bb[j] = Bs[k][tx * 4 + j];
#pragma unroll
            for (int i = 0; i < 8; i++)
#pragma unroll
                for (int j = 0; j < 4; j++) acc[i][j] = fmaf(a[i], bb[j], acc[i][j]);
        }
        __syncthreads();
    }
#pragma unroll
    for (int i = 0; i < 8; i++) {
        size_t row = (size_t)(bm + ty * 8 + i) * 512;
#pragma unroll
        for (int j = 0; j < 4; j++) {
            int col = bn + tx * 4 + j;
            g_encproj_h[row + col] = __float2half_rn(acc[i][j] + bias[col]);
        }
    }
}

// ---------------- K1: gates GEMM, split-K ----------------
// C[64, 2048] = X[64, 1280] @ Wcat[2048, 1280]^T,  X = [x_t | ha | h]
// grid (32 n-tiles, 4 k-chunks of 320), block 256, 64x64 tile, 4x4 per thread
__global__ void k_gates(const float* __restrict__ input_, const float* __restrict__ w_ih,
                        const float* __restrict__ w_hh, int cur, int t) {
    __shared__ float As[16][68];   // [kk][b]
    __shared__ float Bs[16][68];   // [kk][n]
    const int kc = blockIdx.y;
    const int n0 = blockIdx.x * 64;
    const int tid = threadIdx.x;
    const int lb = tid >> 2;          // 0..63
    const int kg = (tid & 3) * 4;     // 0,4,8,12
    const int ty = tid >> 4, tx = tid & 15;

    float acc[4][4];
#pragma unroll
    for (int i = 0; i < 4; i++)
#pragma unroll
        for (int j = 0; j < 4; j++) acc[i][j] = 0.f;

    for (int k0 = kc * 320; k0 < kc * 320 + 320; k0 += 16) {
        int k = k0 + kg;
        // A tile: X[lb][k..k+3]
        float4 av;
        if (k < IN)            av = *(const float4*)&input_[((size_t)lb * T + t) * IN + k];
        else if (k < IN + TRG) av = *(const float4*)&g_ha[cur][lb * TRG + k - IN];
        else                   av = *(const float4*)&g_h[cur][lb * TRG + k - IN - TRG];
        As[kg + 0][lb] = av.x; As[kg + 1][lb] = av.y;
        As[kg + 2][lb] = av.z; As[kg + 3][lb] = av.w;
        // B tile: Wcat[n0+lb][k..k+3]
        float4 bv;
        int n = n0 + lb;
        if (k < IN + TRG) bv = *(const float4*)&w_ih[(size_t)n * (IN + TRG) + k];
        else              bv = *(const float4*)&w_hh[(size_t)n * TRG + k - IN - TRG];
        Bs[kg + 0][lb] = bv.x; Bs[kg + 1][lb] = bv.y;
        Bs[kg + 2][lb] = bv.z; Bs[kg + 3][lb] = bv.w;
        __syncthreads();
#pragma unroll
        for (int kk = 0; kk < 16; kk++) {
            float a[4], bb[4];
#pragma unroll
            for (int i = 0; i < 4; i++) a[i] = As[kk][ty * 4 + i];
#pragma unroll
            for (int j = 0; j < 4; j++) bb[j] = Bs[kk][tx * 4 + j];
#pragma unroll
            for (int i = 0; i < 4; i++)
#pragma unroll
                for (int j = 0; j < 4; j++) acc[i][j] = fmaf(a[i], bb[j], acc[i][j]);
        }
        __syncthreads();
    }
    float* dst = g_gates4[kc];
#pragma unroll
    for (int i = 0; i < 4; i++)
#pragma unroll
        for (int j = 0; j < 4; j++)
            dst[(ty * 4 + i) * G4 + n0 + tx * 4 + j] = acc[i][j];
}

// ---------------- K2: gate-sum + LSTM pointwise + hde GEMV (fused) ----------------
// grid 64 (b), block 512
__global__ void k_lstm_hde(const float* __restrict__ b_ih, const float* __restrict__ b_hh,
                           const float* __restrict__ w_de, int cur) {
    __shared__ __align__(16) float hv[TRG];
    const int b = blockIdx.x, j = threadIdx.x;
    const int nxt = cur ^ 1;
    float gi = b_ih[j] + b_hh[j];
    float gf = b_ih[TRG + j] + b_hh[TRG + j];
    float gg = b_ih[2 * TRG + j] + b_hh[2 * TRG + j];
    float go = b_ih[3 * TRG + j] + b_hh[3 * TRG + j];
#pragma unroll
    for (int kc = 0; kc < 4; kc++) {
        const float* gp = g_gates4[kc] + b * G4;
        gi += gp[j]; gf += gp[TRG + j]; gg += gp[2 * TRG + j]; go += gp[3 * TRG + j];
    }
    float cn = sigmoidf_(gf) * g_c[cur][b * TRG + j] + sigmoidf_(gi) * tanhf(gg);
    float hn = sigmoidf_(go) * tanhf(cn);
    g_c[nxt][b * TRG + j] = cn;
    g_h[nxt][b * TRG + j] = hn;
    hv[j] = hn;
    __syncthreads();
    // hde = h_new @ w_de^T : 16 warps, each does 32 outputs
    const int warp = j >> 5, lane = j & 31;
    const float4* h4 = (const float4*)hv;
    for (int r = 0; r < 32; r++) {
        int jo = warp * 32 + r;
        const float4* w4 = (const float4*)&w_de[(size_t)jo * TRG];
        float a = 0.f;
#pragma unroll
        for (int i = 0; i < 4; i++) {
            int idx = lane + i * 32;
            float4 w = w4[idx], h = h4[idx];
            a += w.x * h.x + w.y * h.y + w.z * h.z + w.w * h.w;
        }
        a = warp_red_sum(a);
        if (lane == 0) g_hde[b * TRG + jo] = a;
    }
}

// ---------------- K3: attn_ee[b,s] = sum_h tanh(ep + hde + pa*cv) * warp_w ----------------
// grid (S/8=128, B), block 256 (warp per s), fp16 enc_proj
__global__ void k_attnee(const float* __restrict__ cv_w, const float* __restrict__ warp_w, int cur) {
    __shared__ __align__(16) float sh_hde[TRG], sh_cv[TRG], sh_w[TRG];
    const int b = blockIdx.y, tid = threadIdx.x;
    for (int i = tid; i < TRG; i += 256) {
        sh_hde[i] = g_hde[b * TRG + i];
        sh_cv[i]  = cv_w[i];
        sh_w[i]   = warp_w[i];
    }
    __syncthreads();
    const int warp = tid >> 5, lane = tid & 31;
    const int s = blockIdx.x * 8 + warp;
    const float pa = g_pa[cur][b * S + s];
    const __half2* ep2 = (const __half2*)(g_encproj_h + ((size_t)b * S + s) * TRG);
    const float2* hd2 = (const float2*)sh_hde;
    const float2* cv2 = (const float2*)sh_cv;
    const float2* ww2 = (const float2*)sh_w;
    float acc = 0.f;
#pragma unroll
    for (int p = 0; p < 8; p++) {
        int i2 = lane + p * 32;
        float2 e  = __half22float2(ep2[i2]);
        float2 hd = hd2[i2], cv = cv2[i2], ww = ww2[i2];
        acc = fmaf(tanh_ap(e.x + hd.x + pa * cv.x), ww.x, acc);
        acc = fmaf(tanh_ap(e.y + hd.y + pa * cv.y), ww.y, acc);
    }
    acc = warp_red_sum(acc);
    if (lane == 0) g_attn[b * S + s] = acc;
}

// ---------------- K4: softmax over S + pa update + attns output ----------------
__global__ void k_softmax(float* __restrict__ out_attn_t, int cur) {
    const int b = blockIdx.x, s = threadIdx.x;
    const int lane = s & 31, warp = s >> 5;
    const int nxt = cur ^ 1;
    __shared__ float red[32];
    float v = g_attn[b * S + s];
    float m = v;
#pragma unroll
    for (int o = 16; o; o >>= 1) m = fmaxf(m, __shfl_xor_sync(0xffffffffu, m, o));
    if (lane == 0) red[warp] = m;
    __syncthreads();
    if (warp == 0) {
        float mm = red[lane];
#pragma unroll
        for (int o = 16; o; o >>= 1) mm = fmaxf(mm, __shfl_xor_sync(0xffffffffu, mm, o));
        if (lane == 0) red[0] = mm;
    }
    __syncthreads();
    m = red[0];
    __syncthreads();
    float e = __expf(v - m);
    float sum = warp_red_sum(e);
    if (lane == 0) red[warp] = sum;
    __syncthreads();
    if (warp == 0) {
        float ss = red[lane];
#pragma unroll
        for (int o = 16; o; o >>= 1) ss += __shfl_xor_sync(0xffffffffu, ss, o);
        if (lane == 0) red[0] = ss;
    }
    __syncthreads();
    float a = e / red[0];
    g_attn[b * S + s] = a;
    out_attn_t[(size_t)b * S + s] = a;
    g_pa[nxt][b * S + s] = g_pa[cur][b * S + s] + a;
}

// ---------------- K5: c_enc partials: c_enc[b,e] = sum_s attn[b,s]*enc[b,s,e] ----------------
// grid (4, B), block 256: each block 256 s-rows, thread owns a half2 column pair
__global__ void k_cenc() {
    __shared__ float sat[256];
    const int b = blockIdx.y;
    const int s0 = blockIdx.x * 256;
    const int tid = threadIdx.x;
    sat[tid] = g_attn[b * S + s0 + tid];
    __syncthreads();
    const __half2* e2 = (const __half2*)g_enc_h + ((size_t)(b * S + s0)) * (ENC / 2) + tid;
    float ax = 0.f, ay = 0.f;
#pragma unroll 4
    for (int s = 0; s < 256; s++) {
        float2 f = __half22float2(e2[(size_t)s * (ENC / 2)]);
        float w = sat[s];
        ax = fmaf(w, f.x, ax);
        ay = fmaf(w, f.y, ay);
    }
    float* dst = g_cenc4[blockIdx.x] + b * TRG + tid * 2;
    dst[0] = ax; dst[1] = ay;
}

// ---------------- K6: ha = [c_enc, h] @ w_ao^T + b_ao; p_gen (fused) ----------------
// grid (65, B): x<64 -> ha (8 outputs/warp-block), x==64 -> pgen
__global__ void k_ha_pgen(const float* __restrict__ w_ao, const float* __restrict__ b_ao,
                          const float* __restrict__ input_, const float* __restrict__ w_pt,
                          const float* __restrict__ b_pt, float* __restrict__ out,
                          int cur, int t) {
    const int b = blockIdx.y, tid = threadIdx.x;
    const int nxt = cur ^ 1;
    if (blockIdx.x < 64) {
        __shared__ __align__(16) float v[ENC + TRG];
        for (int i = tid; i < TRG; i += 256) {
            float cv = g_cenc4[0][b * TRG + i] + g_cenc4[1][b * TRG + i]
                     + g_cenc4[2][b * TRG + i] + g_cenc4[3][b * TRG + i];
            v[i] = cv;
            v[TRG + i] = g_h[nxt][b * TRG + i];
        }
        __syncthreads();
        const int warp = tid >> 5, lane = tid & 31;
        const int j = blockIdx.x * 8 + warp;
        const float4* w = (const float4*)(w_ao + (size_t)j * (ENC + TRG));
        const float4* v4 = (const float4*)v;
        float acc = 0.f;
#pragma unroll
        for (int i = 0; i < 8; i++) {
            int idx = lane + i * 32;
            float4 w4 = w[idx], x4 = v4[idx];
            acc += w4.x * x4.x + w4.y * x4.y + w4.z * x4.z + w4.w * x4.w;
        }
        acc = warp_red_sum(acc);
        if (lane == 0) {
            float r = acc + b_ao[j];
            g_ha[nxt][b * TRG + j] = r;
            out[OUT_OFF + ((size_t)b * T + t) * TRG + j] = r;
        }
    } else {
        // p_gen = sigmoid([x_t, h_new, c_enc] @ w_pt^T + b_pt)
        __shared__ float red[8];
        float acc = 0.f;
        for (int k = tid; k < IN + TRG + TRG; k += 256) {
            float x;
            if (k < IN)            x = input_[((size_t)b * T + t) * IN + k];
            else if (k < IN + TRG) x = g_h[nxt][b * TRG + k - IN];
            else {
                int i = k - IN - TRG;
                x = g_cenc4[0][b * TRG + i] + g_cenc4[1][b * TRG + i]
                  + g_cenc4[2][b * TRG + i] + g_cenc4[3][b * TRG + i];
            }
            acc = fmaf(w_pt[k], x, acc);
        }
        acc = warp_red_sum(acc);
        const int warp = tid >> 5, lane = tid & 31;
        if (lane == 0) red[warp] = acc;
        __syncthreads();
        if (tid == 0) {
            float ss = 0.f;
#pragma unroll
            for (int i = 0; i < 8; i++) ss += red[i];
            out[PGEN_OFF + (size_t)b * T + t] = sigmoidf_(ss + b_pt[0]);
        }
    }
}

// ---------------- finalize ----------------
__global__ void k_final(float* __restrict__ out, const float* __restrict__ past_dehy) {
    int i = blockIdx.x * blockDim.x + threadIdx.x;
    if (i < B * TRG) {
        out[HT_OFF + i]  = g_h[0][i];
        out[CT_OFF + i]  = g_c[0][i];
        out[HAT_OFF + i] = g_ha[0][i];
        out[PDH_OFF + i] = past_dehy[i];
    }
    if (i < B * S) out[PAT_OFF + i] = g_pa[0][i];
    if (i == 0) out[LOSS_OFF] = 0.f;
}

// ---------------- launch ----------------
extern "C" void kernel_launch(void* const* d_in, const int* in_sizes, int n_in,
                              void* d_out, int out_size) {
    const float* input_    = (const float*)d_in[1];
    const float* h0        = (const float*)d_in[2];
    const float* c0        = (const float*)d_in[3];
    const float* h_attn    = (const float*)d_in[4];
    const float* enc       = (const float*)d_in[5];
    const float* past_attn = (const float*)d_in[6];
    const float* past_dehy = (const float*)d_in[7];
    const float* w_ih      = (const float*)d_in[8];
    const float* b_ih      = (const float*)d_in[9];
    const float* w_hh      = (const float*)d_in[10];
    const float* b_hh      = (const float*)d_in[11];
    const float* w_en      = (const float*)d_in[12];
    const float* b_en      = (const float*)d_in[13];
    const float* w_de      = (const float*)d_in[14];
    const float* w_cv      = (const float*)d_in[15];
    const float* w_warp    = (const float*)d_in[16];
    const float* w_ao      = (const float*)d_in[17];
    const float* b_ao      = (const float*)d_in[18];
    const float* w_pt      = (const float*)d_in[19];
    const float* b_pt      = (const float*)d_in[20];
    float* out = (float*)d_out;

    k_init<<<(B * S + 255) / 256, 256>>>(h0, c0, h_attn, past_attn);
    k_conv<<<(B * S * ENC) / (256 * 4), 256>>>(enc);
    k_encproj<<<dim3(TRG / 64, (B * S) / 128), 256>>>(enc, w_en, b_en);

    for (int t = 0; t < T; t++) {
        int cur = t & 1;
        k_gates<<<dim3(32, 4), 256>>>(input_, w_ih, w_hh, cur, t);
        k_lstm_hde<<<64, 512>>>(b_ih, b_hh, w_de, cur);
        k_attnee<<<dim3(S / 8, B), 256>>>(w_cv, w_warp, cur);
        k_softmax<<<B, S>>>(out + ATTN_OFF + (size_t)t * B * S, cur);
        k_cenc<<<dim3(4, B), 256>>>();
        k_ha_pgen<<<dim3(65, B), 256>>>(w_ao, b_ao, input_, w_pt, b_pt, out, cur, t);
    }
    k_final<<<(B * S + 255) / 256, 256>>>(out, past_dehy);
}

// round 4
// speedup vs baseline: 1.4229x; 1.0619x over previous
#include <cuda_runtime.h>
#include <cuda_fp16.h>
#include <math.h>

// Problem constants
#define B   64
#define T   100
#define S   1024
#define IN  256
#define TRG 512
#define ENC 512
#define G4  2048   // 4*TRG

// Output layout offsets (floats)
#define OUT_OFF   0
#define HT_OFF    3276800
#define CT_OFF    3309568
#define HAT_OFF   3342336
#define ATTN_OFF  3375104
#define PAT_OFF   9928704
#define PGEN_OFF  9994240
#define PDH_OFF   10000640
#define LOSS_OFF  10033408

// ---------------- device state ----------------
__device__ __align__(16) __half  g_encproj_h[(size_t)B * S * TRG];   // 67 MB
__device__ __align__(16) __half  g_enc_h[(size_t)B * S * ENC];       // 67 MB
__device__ __align__(16) __half  g_wen_h[512 * 512];
__device__ __align__(16) __half  g_input_h[B * T * IN];
__device__ __align__(16) __half  g_wihx_h[G4 * IN];
__device__ __align__(16) float   g_xg[(size_t)B * T * G4];           // 52 MB
__device__ __align__(16) float g_h[2][B * TRG];
__device__ __align__(16) float g_c[2][B * TRG];
__device__ __align__(16) float g_ha[2][B * TRG];
__device__ __align__(16) float g_pa[2][B * S];
__device__ __align__(16) float g_gatesP[16][B * G4];                 // split-K partials
__device__ __align__(16) float g_hde[B * TRG];
__device__ __align__(16) float g_attn[B * S];
__device__ __align__(16) float g_cenc4[4][B * TRG];

__device__ __forceinline__ float warp_red_sum(float v) {
#pragma unroll
    for (int o = 16; o; o >>= 1) v += __shfl_xor_sync(0xffffffffu, v, o);
    return v;
}
__device__ __forceinline__ float sigmoidf_(float x) { return 1.0f / (1.0f + expf(-x)); }
__device__ __forceinline__ float tanh_ap(float x) {
    float y; asm("tanh.approx.f32 %0, %1;" : "=f"(y) : "f"(x)); return y;
}
__device__ __forceinline__ unsigned smem_u32(const void* p) {
    return (unsigned)__cvta_generic_to_shared(p);
}

// ---------------- init ----------------
__global__ void k_init(const float* __restrict__ h0, const float* __restrict__ c0,
                       const float* __restrict__ h_attn, const float* __restrict__ past_attn) {
    int i = blockIdx.x * blockDim.x + threadIdx.x;
    if (i < B * TRG) { g_h[0][i] = h0[i]; g_c[0][i] = c0[i]; g_ha[0][i] = h_attn[i]; }
    if (i < B * S) g_pa[0][i] = past_attn[i];
}

// ---------------- generic f32 -> f16 (n multiple of 1024) ----------------
__global__ void k_f2h(const float* __restrict__ src, __half* __restrict__ dst) {
    size_t i = ((size_t)blockIdx.x * blockDim.x + threadIdx.x) * 4;
    float4 v = *(const float4*)&src[i];
    __half2* d = (__half2*)&dst[i];
    d[0] = __floats2half2_rn(v.x, v.y);
    d[1] = __floats2half2_rn(v.z, v.w);
}

// w_ih[:, 0:256] (row stride 768) -> compact fp16 [2048][256]
__global__ void k_wihx(const float* __restrict__ w_ih) {
    int n = blockIdx.x;
    for (int c = threadIdx.x; c < IN; c += 64)
        g_wihx_h[n * IN + c] = __float2half_rn(w_ih[(size_t)n * (IN + TRG) + c]);
}

// ---------------- fp16 tensor-core GEMM ----------------
// C[m,n] = sum_k A[m,k] * W[n,k] (+ bias[n] if OUT16)
// block tile 128(M) x 64(N), K chunk 64, 256 threads = 8 warps (4M x 2N)
template<bool OUT16>
__global__ void k_mma(const __half* __restrict__ A, const __half* __restrict__ W,
                      const float* __restrict__ bias, void* __restrict__ Cout,
                      int K, int ldc) {
    __shared__ __align__(16) char smem_raw[128 * 68 * 4];  // 34816 B
    __shared__ float sBias[64];
    __half (*sA)[72] = (__half(*)[72])smem_raw;                       // 128x72 = 18432 B
    __half (*sB)[72] = (__half(*)[72])(smem_raw + 18432);             // 64x72  =  9216 B

    const int m0 = blockIdx.y * 128;
    const int n0 = blockIdx.x * 64;
    const int tid = threadIdx.x;
    const int lane = tid & 31;
    const int w = tid >> 5;
    const int wm = (w >> 1) * 32;   // warp m-base within block
    const int wn = (w & 1) * 32;    // warp n-base within block

    if (OUT16 && tid < 64) sBias[tid] = bias[n0 + tid];

    float c[2][4][4];
#pragma unroll
    for (int i = 0; i < 2; i++)
#pragma unroll
        for (int j = 0; j < 4; j++)
#pragma unroll
            for (int q = 0; q < 4; q++) c[i][j][q] = 0.f;

    const int lrow = lane & 15;
    const int lcol = (lane >> 4) * 8;

    for (int k0 = 0; k0 < K; k0 += 64) {
        __syncthreads();
        {
            int r = tid >> 3, cc = (tid & 7) * 8;
#pragma unroll
            for (int p = 0; p < 4; p++)
                *(float4*)&sA[r + p * 32][cc] =
                    *(const float4*)&A[(size_t)(m0 + r + p * 32) * K + k0 + cc];
#pragma unroll
            for (int p = 0; p < 2; p++)
                *(float4*)&sB[r + p * 32][cc] =
                    *(const float4*)&W[(size_t)(n0 + r + p * 32) * K + k0 + cc];
        }
        __syncthreads();
#pragma unroll
        for (int kk = 0; kk < 4; kk++) {
            unsigned a[2][4], bf[4][2];
#pragma unroll
            for (int mt = 0; mt < 2; mt++) {
                unsigned addr = smem_u32(&sA[wm + mt * 16 + lrow][kk * 16 + lcol]);
                asm volatile("ldmatrix.sync.aligned.m8n8.x4.shared.b16 {%0,%1,%2,%3}, [%4];"
                             : "=r"(a[mt][0]), "=r"(a[mt][1]), "=r"(a[mt][2]), "=r"(a[mt][3])
                             : "r"(addr));
            }
#pragma unroll
            for (int bp = 0; bp < 2; bp++) {
                unsigned r0, r1, r2, r3;
                unsigned addr = smem_u32(&sB[wn + bp * 16 + lrow][kk * 16 + lcol]);
                asm volatile("ldmatrix.sync.aligned.m8n8.x4.shared.b16 {%0,%1,%2,%3}, [%4];"
                             : "=r"(r0), "=r"(r1), "=r"(r2), "=r"(r3) : "r"(addr));
                bf[bp * 2 + 0][0] = r0; bf[bp * 2 + 0][1] = r2;
                bf[bp * 2 + 1][0] = r1; bf[bp * 2 + 1][1] = r3;
            }
#pragma unroll
            for (int mt = 0; mt < 2; mt++)
#pragma unroll
                for (int nf = 0; nf < 4; nf++) {
                    asm volatile(
                        "mma.sync.aligned.m16n8k16.row.col.f32.f16.f16.f32 "
                        "{%0,%1,%2,%3}, {%4,%5,%6,%7}, {%8,%9}, {%0,%1,%2,%3};"
                        : "+f"(c[mt][nf][0]), "+f"(c[mt][nf][1]),
                          "+f"(c[mt][nf][2]), "+f"(c[mt][nf][3])
                        : "r"(a[mt][0]), "r"(a[mt][1]), "r"(a[mt][2]), "r"(a[mt][3]),
                          "r"(bf[nf][0]), "r"(bf[nf][1]));
                }
        }
    }
    // epilogue: stage f32 in smem (row pad 68 floats = 272B, 16B-aligned rows)
    __syncthreads();
    float (*sO)[68] = (float(*)[68])smem_raw;
    {
        int g = lane >> 2, tq = lane & 3;
#pragma unroll
        for (int mt = 0; mt < 2; mt++)
#pragma unroll
            for (int nf = 0; nf < 4; nf++) {
                int r = wm + mt * 16 + g;
                int cc = wn + (nf >> 1) * 16 + (nf & 1) * 8 + tq * 2;
                sO[r][cc]     = c[mt][nf][0]; sO[r][cc + 1]     = c[mt][nf][1];
                sO[r + 8][cc] = c[mt][nf][2]; sO[r + 8][cc + 1] = c[mt][nf][3];
            }
    }
    __syncthreads();
#pragma unroll
    for (int p = 0; p < 4; p++) {
        int idx = p * 256 + tid;
        int r = idx >> 3, c8 = (idx & 7) * 8;
        if (OUT16) {
            __half* C = (__half*)Cout;
            __half2 h[4];
#pragma unroll
            for (int q = 0; q < 4; q++)
                h[q] = __floats2half2_rn(sO[r][c8 + 2 * q] + sBias[c8 + 2 * q],
                                         sO[r][c8 + 2 * q + 1] + sBias[c8 + 2 * q + 1]);
            *(float4*)&C[(size_t)(m0 + r) * ldc + n0 + c8] = *(float4*)h;
        } else {
            float* C = (float*)Cout;
            *(float4*)&C[(size_t)(m0 + r) * ldc + n0 + c8]     = *(float4*)&sO[r][c8];
            *(float4*)&C[(size_t)(m0 + r) * ldc + n0 + c8 + 4] = *(float4*)&sO[r][c8 + 4];
        }
    }
}

// ---------------- K1: recurrent gates GEMM, split-K=16 ----------------
// P[kc][64, 2048] = X[64, k in chunk] @ Wr^T,  X = [ha | h] (K=1024)
__global__ void k_gates(const float* __restrict__ w_ih, const float* __restrict__ w_hh,
                        int cur) {
    __shared__ float As[16][68];
    __shared__ float Bs[16][132];
    const int kc = blockIdx.y;
    const int n0 = blockIdx.x * 128;
    const int tid = threadIdx.x;
    const int ty = tid >> 4, tx = tid & 15;

    float acc[4][8];
#pragma unroll
    for (int i = 0; i < 4; i++)
#pragma unroll
        for (int j = 0; j < 8; j++) acc[i][j] = 0.f;

#pragma unroll
    for (int sub = 0; sub < 4; sub++) {
        const int kbase = kc * 64 + sub * 16;
        __syncthreads();
        {
            int b = tid >> 2, c4 = (tid & 3) * 4;
            int k = kbase + c4;
            float4 av = (k < TRG) ? *(const float4*)&g_ha[cur][b * TRG + k]
                                  : *(const float4*)&g_h[cur][b * TRG + k - TRG];
            As[c4 + 0][b] = av.x; As[c4 + 1][b] = av.y;
            As[c4 + 2][b] = av.z; As[c4 + 3][b] = av.w;
        }
#pragma unroll
        for (int ppp = 0; ppp < 2; ppp++) {
            int idx = tid + ppp * 256;
            int r = idx >> 2, c4 = (idx & 3) * 4;
            int n = n0 + r, k = kbase + c4;
            float4 bv = (k < TRG) ? *(const float4*)&w_ih[(size_t)n * (IN + TRG) + IN + k]
                                  : *(const float4*)&w_hh[(size_t)n * TRG + k - TRG];
            Bs[c4 + 0][r] = bv.x; Bs[c4 + 1][r] = bv.y;
            Bs[c4 + 2][r] = bv.z; Bs[c4 + 3][r] = bv.w;
        }
        __syncthreads();
#pragma unroll
        for (int kk = 0; kk < 16; kk++) {
            float a[4], bb[8];
#pragma unroll
            for (int i = 0; i < 4; i++) a[i] = As[kk][ty + 16 * i];
#pragma unroll
            for (int j = 0; j < 8; j++) bb[j] = Bs[kk][tx + 16 * j];
#pragma unroll
            for (int i = 0; i < 4; i++)
#pragma unroll
                for (int j = 0; j < 8; j++) acc[i][j] = fmaf(a[i], bb[j], acc[i][j]);
        }
    }
    float* dst = g_gatesP[kc];
#pragma unroll
    for (int i = 0; i < 4; i++)
#pragma unroll
        for (int j = 0; j < 8; j++)
            dst[(ty + 16 * i) * G4 + n0 + tx + 16 * j] = acc[i][j];
}

// ---------------- K2: partial-sum + xg + LSTM + hde GEMV (fused) ----------------
__global__ void k_lstm_hde(const float* __restrict__ b_ih, const float* __restrict__ b_hh,
                           const float* __restrict__ w_de, int cur, int t) {
    __shared__ __align__(16) float hv[TRG];
    const int b = blockIdx.x, j = threadIdx.x;
    const int nxt = cur ^ 1;
    const float* xgp = g_xg + ((size_t)b * T + t) * G4;
    float gi = b_ih[j]           + b_hh[j]           + xgp[j];
    float gf = b_ih[TRG + j]     + b_hh[TRG + j]     + xgp[TRG + j];
    float gg = b_ih[2 * TRG + j] + b_hh[2 * TRG + j] + xgp[2 * TRG + j];
    float go = b_ih[3 * TRG + j] + b_hh[3 * TRG + j] + xgp[3 * TRG + j];
#pragma unroll
    for (int kc = 0; kc < 16; kc++) {
        const float* gp = g_gatesP[kc] + b * G4;
        gi += gp[j]; gf += gp[TRG + j]; gg += gp[2 * TRG + j]; go += gp[3 * TRG + j];
    }
    float cn = sigmoidf_(gf) * g_c[cur][b * TRG + j] + sigmoidf_(gi) * tanhf(gg);
    float hn = sigmoidf_(go) * tanhf(cn);
    g_c[nxt][b * TRG + j] = cn;
    g_h[nxt][b * TRG + j] = hn;
    hv[j] = hn;
    __syncthreads();
    const int warp = j >> 5, lane = j & 31;
    const float4* h4 = (const float4*)hv;
    for (int r = 0; r < 32; r++) {
        int jo = warp * 32 + r;
        const float4* w4 = (const float4*)&w_de[(size_t)jo * TRG];
        float a = 0.f;
#pragma unroll
        for (int i = 0; i < 4; i++) {
            int idx = lane + i * 32;
            float4 wv = w4[idx], hh = h4[idx];
            a += wv.x * hh.x + wv.y * hh.y + wv.z * hh.z + wv.w * hh.w;
        }
        a = warp_red_sum(a);
        if (lane == 0) g_hde[b * TRG + jo] = a;
    }
}

// ---------------- K3: attn_ee[b,s] = sum_h tanh(ep + hde + pa*cv) * warp_w ----------------
__global__ void k_attnee(const float* __restrict__ cv_w, const float* __restrict__ warp_w, int cur) {
    __shared__ __align__(16) float sh_hde[TRG], sh_cv[TRG], sh_w[TRG];
    const int b = blockIdx.y, tid = threadIdx.x;
    for (int i = tid; i < TRG; i += 256) {
        sh_hde[i] = g_hde[b * TRG + i];
        sh_cv[i]  = cv_w[i];
        sh_w[i]   = warp_w[i];
    }
    __syncthreads();
    const int warp = tid >> 5, lane = tid & 31;
    const int s = blockIdx.x * 8 + warp;
    const float pa = g_pa[cur][b * S + s];
    const __half2* ep2 = (const __half2*)(g_encproj_h + ((size_t)b * S + s) * TRG);
    const float2* hd2 = (const float2*)sh_hde;
    const float2* cv2 = (const float2*)sh_cv;
    const float2* ww2 = (const float2*)sh_w;
    float acc = 0.f;
#pragma unroll
    for (int p = 0; p < 8; p++) {
        int i2 = lane + p * 32;
        float2 e  = __half22float2(ep2[i2]);
        float2 hd = hd2[i2], cv = cv2[i2], ww = ww2[i2];
        acc = fmaf(tanh_ap(e.x + hd.x + pa * cv.x), ww.x, acc);
        acc = fmaf(tanh_ap(e.y + hd.y + pa * cv.y), ww.y, acc);
    }
    acc = warp_red_sum(acc);
    if (lane == 0) g_attn[b * S + s] = acc;
}

// ---------------- K4: softmax over S + pa update + attns output ----------------
__global__ void k_softmax(float* __restrict__ out_attn_t, int cur) {
    const int b = blockIdx.x, s = threadIdx.x;
    const int lane = s & 31, warp = s >> 5;
    const int nxt = cur ^ 1;
    __shared__ float red[32];
    float v = g_attn[b * S + s];
    float m = v;
#pragma unroll
    for (int o = 16; o; o >>= 1) m = fmaxf(m, __shfl_xor_sync(0xffffffffu, m, o));
    if (lane == 0) red[warp] = m;
    __syncthreads();
    if (warp == 0) {
        float mm = red[lane];
#pragma unroll
        for (int o = 16; o; o >>= 1) mm = fmaxf(mm, __shfl_xor_sync(0xffffffffu, mm, o));
        if (lane == 0) red[0] = mm;
    }
    __syncthreads();
    m = red[0];
    __syncthreads();
    float e = __expf(v - m);
    float sum = warp_red_sum(e);
    if (lane == 0) red[warp] = sum;
    __syncthreads();
    if (warp == 0) {
        float ss = red[lane];
#pragma unroll
        for (int o = 16; o; o >>= 1) ss += __shfl_xor_sync(0xffffffffu, ss, o);
        if (lane == 0) red[0] = ss;
    }
    __syncthreads();
    float a = e / red[0];
    g_attn[b * S + s] = a;
    out_attn_t[(size_t)b * S + s] = a;
    g_pa[nxt][b * S + s] = g_pa[cur][b * S + s] + a;
}

// ---------------- K5: c_enc partials ----------------
__global__ void k_cenc() {
    __shared__ float sat[256];
    const int b = blockIdx.y;
    const int s0 = blockIdx.x * 256;
    const int tid = threadIdx.x;
    sat[tid] = g_attn[b * S + s0 + tid];
    __syncthreads();
    const __half2* e2 = (const __half2*)g_enc_h + ((size_t)(b * S + s0)) * (ENC / 2) + tid;
    float ax = 0.f, ay = 0.f;
#pragma unroll 4
    for (int s = 0; s < 256; s++) {
        float2 f = __half22float2(e2[(size_t)s * (ENC / 2)]);
        float w = sat[s];
        ax = fmaf(w, f.x, ax);
        ay = fmaf(w, f.y, ay);
    }
    float* dst = g_cenc4[blockIdx.x] + b * TRG + tid * 2;
    dst[0] = ax; dst[1] = ay;
}

// ---------------- K6: ha = [c_enc, h] @ w_ao^T + b_ao; p_gen (fused) ----------------
__global__ void k_ha_pgen(const float* __restrict__ w_ao, const float* __restrict__ b_ao,
                          const float* __restrict__ input_, const float* __restrict__ w_pt,
                          const float* __restrict__ b_pt, float* __restrict__ out,
                          int cur, int t) {
    const int b = blockIdx.y, tid = threadIdx.x;
    const int nxt = cur ^ 1;
    if (blockIdx.x < 64) {
        __shared__ __align__(16) float v[ENC + TRG];
        for (int i = tid; i < TRG; i += 256) {
            float cv = g_cenc4[0][b * TRG + i] + g_cenc4[1][b * TRG + i]
                     + g_cenc4[2][b * TRG + i] + g_cenc4[3][b * TRG + i];
            v[i] = cv;
            v[TRG + i] = g_h[nxt][b * TRG + i];
        }
        __syncthreads();
        const int warp = tid >> 5, lane = tid & 31;
        const int j = blockIdx.x * 8 + warp;
        const float4* w = (const float4*)(w_ao + (size_t)j * (ENC + TRG));
        const float4* v4 = (const float4*)v;
        float acc = 0.f;
#pragma unroll
        for (int i = 0; i < 8; i++) {
            int idx = lane + i * 32;
            float4 w4 = w[idx], x4 = v4[idx];
            acc += w4.x * x4.x + w4.y * x4.y + w4.z * x4.z + w4.w * x4.w;
        }
        acc = warp_red_sum(acc);
        if (lane == 0) {
            float r = acc + b_ao[j];
            g_ha[nxt][b * TRG + j] = r;
            out[OUT_OFF + ((size_t)b * T + t) * TRG + j] = r;
        }
    } else {
        __shared__ float red[8];
        float acc = 0.f;
        for (int k = tid; k < IN + TRG + TRG; k += 256) {
            float x;
            if (k < IN)            x = input_[((size_t)b * T + t) * IN + k];
            else if (k < IN + TRG) x = g_h[nxt][b * TRG + k - IN];
            else {
                int i = k - IN - TRG;
                x = g_cenc4[0][b * TRG + i] + g_cenc4[1][b * TRG + i]
                  + g_cenc4[2][b * TRG + i] + g_cenc4[3][b * TRG + i];
            }
            acc = fmaf(w_pt[k], x, acc);
        }
        acc = warp_red_sum(acc);
        const int warp = tid >> 5, lane = tid & 31;
        if (lane == 0) red[warp] = acc;
        __syncthreads();
        if (tid == 0) {
            float ss = 0.f;
#pragma unroll
            for (int i = 0; i < 8; i++) ss += red[i];
            out[PGEN_OFF + (size_t)b * T + t] = sigmoidf_(ss + b_pt[0]);
        }
    }
}

// ---------------- finalize ----------------
__global__ void k_final(float* __restrict__ out, const float* __restrict__ past_dehy) {
    int i = blockIdx.x * blockDim.x + threadIdx.x;
    if (i < B * TRG) {
        out[HT_OFF + i]  = g_h[0][i];
        out[CT_OFF + i]  = g_c[0][i];
        out[HAT_OFF + i] = g_ha[0][i];
        out[PDH_OFF + i] = past_dehy[i];
    }
    if (i < B * S) out[PAT_OFF + i] = g_pa[0][i];
    if (i == 0) out[LOSS_OFF] = 0.f;
}

// ---------------- launch ----------------
extern "C" void kernel_launch(void* const* d_in, const int* in_sizes, int n_in,
                              void* d_out, int out_size) {
    const float* input_    = (const float*)d_in[1];
    const float* h0        = (const float*)d_in[2];
    const float* c0        = (const float*)d_in[3];
    const float* h_attn    = (const float*)d_in[4];
    const float* enc       = (const float*)d_in[5];
    const float* past_attn = (const float*)d_in[6];
    const float* past_dehy = (const float*)d_in[7];
    const float* w_ih      = (const float*)d_in[8];
    const float* b_ih      = (const float*)d_in[9];
    const float* w_hh      = (const float*)d_in[10];
    const float* b_hh      = (const float*)d_in[11];
    const float* w_en      = (const float*)d_in[12];
    const float* b_en      = (const float*)d_in[13];
    const float* w_de      = (const float*)d_in[14];
    const float* w_cv      = (const float*)d_in[15];
    const float* w_warp    = (const float*)d_in[16];
    const float* w_ao      = (const float*)d_in[17];
    const float* b_ao      = (const float*)d_in[18];
    const float* w_pt      = (const float*)d_in[19];
    const float* b_pt      = (const float*)d_in[20];
    float* out = (float*)d_out;

    __half *p_enc_h, *p_wen_h, *p_input_h, *p_encproj_h, *p_wihx_h;
    float *p_xg;
    cudaGetSymbolAddress((void**)&p_enc_h, g_enc_h);
    cudaGetSymbolAddress((void**)&p_wen_h, g_wen_h);
    cudaGetSymbolAddress((void**)&p_input_h, g_input_h);
    cudaGetSymbolAddress((void**)&p_encproj_h, g_encproj_h);
    cudaGetSymbolAddress((void**)&p_wihx_h, g_wihx_h);
    cudaGetSymbolAddress((void**)&p_xg, g_xg);

    k_init<<<(B * S + 255) / 256, 256>>>(h0, c0, h_attn, past_attn);
    k_f2h<<<(B * S * ENC) / 1024, 256>>>(enc, p_enc_h);
    k_f2h<<<(512 * 512) / 1024, 256>>>(w_en, p_wen_h);
    k_f2h<<<(B * T * IN) / 1024, 256>>>(input_, p_input_h);
    k_wihx<<<G4, 64>>>(w_ih);

    // enc_proj: [65536,512] = enc_h @ wen^T + b_en  -> fp16
    k_mma<true><<<dim3(512 / 64, (B * S) / 128), 256>>>(p_enc_h, p_wen_h, b_en,
                                                        p_encproj_h, 512, 512);
    // xg: [6400,2048] = input_h @ wihx^T -> fp32
    k_mma<false><<<dim3(G4 / 64, (B * T) / 128), 256>>>(p_input_h, p_wihx_h, nullptr,
                                                        p_xg, IN, G4);

    for (int t = 0; t < T; t++) {
        int cur = t & 1;
        k_gates<<<dim3(16, 16), 256>>>(w_ih, w_hh, cur);
        k_lstm_hde<<<64, 512>>>(b_ih, b_hh, w_de, cur, t);
        k_attnee<<<dim3(S / 8, B), 256>>>(w_cv, w_warp, cur);
        k_softmax<<<B, S>>>(out + ATTN_OFF + (size_t)t * B * S, cur);
        k_cenc<<<dim3(4, B), 256>>>();
        k_ha_pgen<<<dim3(65, B), 256>>>(w_ao, b_ao, input_, w_pt, b_pt, out, cur, t);
    }
    k_final<<<(B * S + 255) / 256, 256>>>(out, past_dehy);
}